// round 12
// baseline (speedup 1.0000x reference)
#include <cuda_runtime.h>
#include <math.h>
#include <stdint.h>

// ---------------- scratch (device globals) ---------------------------------
__device__ float g_mixed[8192];
__device__ float g_z[4096];
__device__ float g_beta[32];
__device__ float g_a[32];
__device__ float g_outflat[4096];

#define OFF_STATE 2048
#define OFF_CONV  (2048 + 524288)

// ---------------- ptx helpers ----------------------------------------------
__device__ __forceinline__ uint32_t smem_u32(const void* p) {
    uint32_t a;
    asm("{ .reg .u64 t; cvta.to.shared.u64 t, %1; cvt.u32.u64 %0, t; }"
        : "=r"(a) : "l"(p));
    return a;
}
__device__ __forceinline__ void mbar_init(uint32_t bar, uint32_t cnt) {
    asm volatile("mbarrier.init.shared.b64 [%0], %1;" :: "r"(bar), "r"(cnt) : "memory");
}
__device__ __forceinline__ void mbar_expect_tx(uint32_t bar, uint32_t bytes) {
    asm volatile("mbarrier.arrive.expect_tx.shared.b64 _, [%0], %1;"
                 :: "r"(bar), "r"(bytes) : "memory");
}
__device__ __forceinline__ void bulk_g2s(uint32_t dst, const void* src,
                                         uint32_t bytes, uint32_t bar) {
    asm volatile(
        "cp.async.bulk.shared::cluster.global.mbarrier::complete_tx::bytes "
        "[%0], [%1], %2, [%3];"
        :: "r"(dst), "l"(src), "r"(bytes), "r"(bar) : "memory");
}
__device__ __forceinline__ void mbar_wait(uint32_t bar, uint32_t parity) {
    asm volatile(
        "{\n\t.reg .pred P;\n"
        "W_%=:\n\t"
        "mbarrier.try_wait.parity.shared.b64 P, [%0], %1;\n\t"
        "@P bra D_%=;\n\t"
        "bra W_%=;\n"
        "D_%=:\n\t}"
        :: "r"(bar), "r"(parity) : "memory");
}
__device__ __forceinline__ void bulk_prefetch_l2(const void* src, uint32_t bytes) {
    asm volatile("cp.async.bulk.prefetch.L2.global [%0], %1;"
                 :: "l"(src), "r"(bytes) : "memory");
}

__device__ __forceinline__ float silu_f(float v) { return v / (1.f + expf(-v)); }
__device__ __forceinline__ float softplus_f(float v) {
    return (v > 20.f) ? v : log1pf(expf(v));
}
__device__ __forceinline__ float conv_silu(
    int c, const float* __restrict__ cs, const float* __restrict__ cw)
{
    float v = cs[c * 3 + 0] * cw[c * 4 + 0]
            + cs[c * 3 + 1] * cw[c * 4 + 1]
            + cs[c * 3 + 2] * cw[c * 4 + 2]
            + g_mixed[c]    * cw[c * 4 + 3];
    return silu_f(v);
}
__device__ __forceinline__ float blockSum512(float v, float* red) {
    #pragma unroll
    for (int o = 16; o; o >>= 1) v += __shfl_down_sync(0xffffffffu, v, o);
    int w = threadIdx.x >> 5;
    if ((threadIdx.x & 31) == 0) red[w] = v;
    __syncthreads();
    float r = 0.f;
    #pragma unroll
    for (int i = 0; i < 16; i++) r += red[i];
    __syncthreads();
    return r;
}

// ---------------- K1: ring-2 TMA GEMV + bulk L2 prefetch tail --------------
__global__ __launch_bounds__(256) void k_gemv_in(
    const float* __restrict__ x,
    const float* __restrict__ W_qkv,
    const float* __restrict__ W_z,
    const float* __restrict__ W_b,
    const float* __restrict__ W_a,
    const float* __restrict__ conv_state,
    const float* __restrict__ state,
    const float* __restrict__ W_out,
    float* __restrict__ out)
{
    __shared__ __align__(16)  float sx[2048];
    __shared__ __align__(128) float sw[2][4096];
    __shared__ float sred[2][8][2];
    __shared__ __align__(8) unsigned long long mbar[2];

    int tid  = threadIdx.x;
    int warp = tid >> 5;
    int lane = tid & 31;

    #pragma unroll
    for (int i = 0; i < 2; i++)
        ((float4*)sx)[tid + i * 256] = ((const float4*)x)[tid + i * 256];

    uint32_t mb = smem_u32(&mbar[0]);
    if (tid == 0) { mbar_init(mb, 1); mbar_init(mb + 8, 1); }
    __syncthreads();

    int row0 = blockIdx.x * 16;
    const float* wbase;
    if (row0 < 8192)       wbase = W_qkv + (size_t)row0 * 2048;
    else if (row0 < 12288) wbase = W_z   + (size_t)(row0 - 8192) * 2048;
    else if (row0 < 12320) wbase = W_b   + (size_t)(row0 - 12288) * 2048;
    else                   wbase = W_a   + (size_t)(row0 - 12320) * 2048;

    uint32_t sw0 = smem_u32(&sw[0][0]);
    uint32_t sw1 = smem_u32(&sw[1][0]);

    if (tid == 0) {
        mbar_expect_tx(mb, 16384);
        bulk_g2s(sw0, wbase, 16384, mb);
        mbar_expect_tx(mb + 8, 16384);
        bulk_g2s(sw1, wbase + 4096, 16384, mb + 8);
    }

    const float4* x4 = (const float4*)sx;
    float4 xv0 = x4[tid * 2];
    float4 xv1 = x4[tid * 2 + 1];

    #pragma unroll
    for (int i = 0; i < 8; i++) {
        int p = i & 1;
        mbar_wait(mb + p * 8, (i >> 1) & 1);

        const float4* r0 = (const float4*)&sw[p][0];
        const float4* r1 = (const float4*)&sw[p][2048];
        float4 a0 = r0[tid * 2], a1 = r0[tid * 2 + 1];
        float4 b0 = r1[tid * 2], b1 = r1[tid * 2 + 1];
        float pa = a0.x * xv0.x + a0.y * xv0.y + a0.z * xv0.z + a0.w * xv0.w
                 + a1.x * xv1.x + a1.y * xv1.y + a1.z * xv1.z + a1.w * xv1.w;
        float pb = b0.x * xv0.x + b0.y * xv0.y + b0.z * xv0.z + b0.w * xv0.w
                 + b1.x * xv1.x + b1.y * xv1.y + b1.z * xv1.z + b1.w * xv1.w;
        #pragma unroll
        for (int o = 16; o; o >>= 1) {
            pa += __shfl_down_sync(0xffffffffu, pa, o);
            pb += __shfl_down_sync(0xffffffffu, pb, o);
        }
        if (lane == 0) { sred[p][warp][0] = pa; sred[p][warp][1] = pb; }
        __syncthreads();

        if (tid == 0 && i + 2 < 8) {
            mbar_expect_tx(mb + p * 8, 16384);
            bulk_g2s(p ? sw1 : sw0, wbase + (size_t)(i + 2) * 4096, 16384,
                     mb + p * 8);
        }
        if (tid < 2) {
            float acc = 0.f;
            #pragma unroll
            for (int w = 0; w < 8; w++) acc += sred[p][w][tid];
            int r = row0 + i * 2 + tid;
            if (r < 8192) {
                g_mixed[r] = acc;
                float* nc = out + OFF_CONV + (size_t)r * 3;
                __stcs(&nc[0], conv_state[r * 3 + 1]);
                __stcs(&nc[1], conv_state[r * 3 + 2]);
                __stcs(&nc[2], acc);
            } else if (r < 12288) {
                g_z[r - 8192] = acc;
            } else if (r < 12320) {
                g_beta[r - 12288] = acc;
            } else {
                g_a[r - 12320] = acc;
            }
        }
    }

    // ---- tail: bulk L2 prefetch (TMA path) of W_out + state ----
    if (tid == 0) {
        // W_out: 33554432 bytes over 772 blocks, 43472 B each (16B multiple)
        size_t start = (size_t)blockIdx.x * 43472;
        const size_t wout_bytes = 33554432u;
        if (start < wout_bytes) {
            size_t len = wout_bytes - start;
            if (len > 43472) len = 43472;
            bulk_prefetch_l2((const char*)W_out + start, (uint32_t)len);
        }
        // state: 8388608 bytes over blocks 0..511, 16384 B each
        if (blockIdx.x < 512)
            bulk_prefetch_l2((const char*)state + (size_t)blockIdx.x * 16384,
                             16384u);
    }
}

// ---------------- K2: per-head delta rule (32 blocks x 512) — R5 proven ----
__global__ __launch_bounds__(512) void k_head(
    const float* __restrict__ state,
    const float* __restrict__ conv_state,
    const float* __restrict__ conv_w,
    const float* __restrict__ A_log,
    const float* __restrict__ dt_bias,
    const float* __restrict__ norm_w,
    float* __restrict__ out)
{
    int h   = blockIdx.x;
    int tid = threadIdx.x;
    int cg  = tid & 31;
    int sl  = tid >> 5;

    __shared__ float sq[128], sk[128], sv[128], sdelta[128];
    __shared__ float red[16];
    __shared__ float skv[16][128], ssqv[16][128];

    if (tid < 128) {
        int grp = h >> 1;
        sq[tid] = conv_silu(grp * 128 + tid,        conv_state, conv_w);
        sk[tid] = conv_silu(2048 + grp * 128 + tid, conv_state, conv_w);
        sv[tid] = conv_silu(4096 + h * 128 + tid,   conv_state, conv_w);
    }
    __syncthreads();

    float q2 = blockSum512(tid < 128 ? sq[tid] * sq[tid] : 0.f, red);
    float k2 = blockSum512(tid < 128 ? sk[tid] * sk[tid] : 0.f, red);
    const float inv_sqrt128 = 0.08838834764831845f;
    if (tid < 128) {
        sq[tid] = sq[tid] * rsqrtf(q2 + 1e-6f) * inv_sqrt128;
        sk[tid] = sk[tid] * rsqrtf(k2 + 1e-6f);
    }
    __syncthreads();
    float qk = blockSum512(tid < 128 ? sq[tid] * sk[tid] : 0.f, red);

    float g    = expf(-expf(A_log[h]) * softplus_f(g_a[h] + dt_bias[h]));
    float beta = 1.f / (1.f + expf(-g_beta[h]));

    const float4* S4 = (const float4*)(state + (size_t)h * 16384);
    float4 sg4[8];
    float4 kv  = make_float4(0.f, 0.f, 0.f, 0.f);
    float4 sqv = make_float4(0.f, 0.f, 0.f, 0.f);
    #pragma unroll
    for (int r = 0; r < 8; r++) {
        int kk = sl * 8 + r;
        float4 s = S4[kk * 32 + cg];
        s.x *= g; s.y *= g; s.z *= g; s.w *= g;
        sg4[r] = s;
        float kkv = sk[kk], qqv = sq[kk];
        kv.x  += s.x * kkv; kv.y  += s.y * kkv; kv.z  += s.z * kkv; kv.w  += s.w * kkv;
        sqv.x += s.x * qqv; sqv.y += s.y * qqv; sqv.z += s.z * qqv; sqv.w += s.w * qqv;
    }
    ((float4*)&skv[sl][0])[cg]  = kv;
    ((float4*)&ssqv[sl][0])[cg] = sqv;
    __syncthreads();

    float gated = 0.f;
    if (tid < 128) {
        float kvt = 0.f, sqvt = 0.f;
        #pragma unroll
        for (int s = 0; s < 16; s++) { kvt += skv[s][tid]; sqvt += ssqv[s][tid]; }
        float delta = (sv[tid] - kvt) * beta;
        sdelta[tid] = delta;
        float o = sqvt + delta * qk;
        gated = o * silu_f(g_z[h * 128 + tid]);
    }
    __syncthreads();

    float4 d4 = ((float4*)sdelta)[cg];
    float4* NS4 = (float4*)(out + OFF_STATE + (size_t)h * 16384);
    #pragma unroll
    for (int r = 0; r < 8; r++) {
        int kk = sl * 8 + r;
        float kkv = sk[kk];
        float4 w;
        w.x = sg4[r].x + kkv * d4.x;
        w.y = sg4[r].y + kkv * d4.y;
        w.z = sg4[r].z + kkv * d4.z;
        w.w = sg4[r].w + kkv * d4.w;
        __stcs(&NS4[kk * 32 + cg], w);
    }

    float m = blockSum512(tid < 128 ? gated * gated : 0.f, red) * (1.f / 128.f);
    if (tid < 128)
        g_outflat[h * 128 + tid] = gated * rsqrtf(m + 1e-6f) * norm_w[tid];
}

// ---------------- K3: output GEMV (2048 rows x 4096), 2 warps/row — R5 -----
__global__ __launch_bounds__(256, 4) void k_gemv_out(
    const float* __restrict__ W_out, float* __restrict__ out)
{
    __shared__ float so[4096];
    __shared__ float sred[8];
    int tid = threadIdx.x;
    #pragma unroll
    for (int i = 0; i < 4; i++)
        ((float4*)so)[tid + i * 256] = ((const float4*)g_outflat)[tid + i * 256];
    __syncthreads();

    int warp = tid >> 5;
    int lane = tid & 31;
    int rloc = warp >> 1;
    int half = warp & 1;
    int row  = blockIdx.x * 4 + rloc;

    const float4* w4 = (const float4*)(W_out + (size_t)row * 4096 + half * 2048);
    const float4* x4 = (const float4*)so + half * 512;

    float acc0 = 0.f, acc1 = 0.f;
    #pragma unroll
    for (int i = 0; i < 4; i++) {
        float4 a[4];
        #pragma unroll
        for (int t = 0; t < 4; t++)
            a[t] = __ldg(&w4[(i * 4 + t) * 32 + lane]);
        #pragma unroll
        for (int t = 0; t < 4; t++) {
            float4 v = x4[(i * 4 + t) * 32 + lane];
            acc0 += a[t].x * v.x + a[t].y * v.y;
            acc1 += a[t].z * v.z + a[t].w * v.w;
        }
    }
    float acc = acc0 + acc1;
    #pragma unroll
    for (int o = 16; o; o >>= 1) acc += __shfl_down_sync(0xffffffffu, acc, o);
    if (lane == 0) sred[warp] = acc;
    __syncthreads();
    if (tid < 4)
        out[blockIdx.x * 4 + tid] = sred[tid * 2] + sred[tid * 2 + 1];
}

// ---------------- launcher --------------------------------------------------
extern "C" void kernel_launch(void* const* d_in, const int* in_sizes, int n_in,
                              void* d_out, int out_size)
{
    const float* x          = (const float*)d_in[0];
    const float* state      = (const float*)d_in[1];
    const float* conv_state = (const float*)d_in[2];
    const float* W_qkv      = (const float*)d_in[3];
    const float* W_z        = (const float*)d_in[4];
    const float* W_b        = (const float*)d_in[5];
    const float* W_a        = (const float*)d_in[6];
    const float* conv_w     = (const float*)d_in[7];
    const float* A_log      = (const float*)d_in[8];
    const float* dt_bias    = (const float*)d_in[9];
    const float* norm_w     = (const float*)d_in[10];
    const float* W_out      = (const float*)d_in[11];
    float* out = (float*)d_out;

    k_gemv_in<<<772, 256>>>(x, W_qkv, W_z, W_b, W_a, conv_state,
                            state, W_out, out);
    k_head<<<32, 512>>>(state, conv_state, conv_w, A_log, dt_bias, norm_w, out);
    k_gemv_out<<<512, 256>>>(W_out, out);
}

// round 13
// speedup vs baseline: 1.2626x; 1.2626x over previous
#include <cuda_runtime.h>
#include <math.h>
#include <stdint.h>

// ---------------- scratch (device globals) ---------------------------------
__device__ float g_mixed[8192];
__device__ float g_z[4096];
__device__ float g_beta[32];
__device__ float g_a[32];
__device__ float g_outflat[4096];

#define OFF_STATE 2048
#define OFF_CONV  (2048 + 524288)

// ---------------- ptx helpers ----------------------------------------------
__device__ __forceinline__ uint32_t smem_u32(const void* p) {
    uint32_t a;
    asm("{ .reg .u64 t; cvta.to.shared.u64 t, %1; cvt.u32.u64 %0, t; }"
        : "=r"(a) : "l"(p));
    return a;
}
__device__ __forceinline__ void mbar_init(uint32_t bar, uint32_t cnt) {
    asm volatile("mbarrier.init.shared.b64 [%0], %1;" :: "r"(bar), "r"(cnt) : "memory");
}
__device__ __forceinline__ void mbar_expect_tx(uint32_t bar, uint32_t bytes) {
    asm volatile("mbarrier.arrive.expect_tx.shared.b64 _, [%0], %1;"
                 :: "r"(bar), "r"(bytes) : "memory");
}
__device__ __forceinline__ void bulk_g2s(uint32_t dst, const void* src,
                                         uint32_t bytes, uint32_t bar) {
    asm volatile(
        "cp.async.bulk.shared::cluster.global.mbarrier::complete_tx::bytes "
        "[%0], [%1], %2, [%3];"
        :: "r"(dst), "l"(src), "r"(bytes), "r"(bar) : "memory");
}
__device__ __forceinline__ void mbar_wait(uint32_t bar, uint32_t parity) {
    asm volatile(
        "{\n\t.reg .pred P;\n"
        "W_%=:\n\t"
        "mbarrier.try_wait.parity.shared.b64 P, [%0], %1;\n\t"
        "@P bra D_%=;\n\t"
        "bra W_%=;\n"
        "D_%=:\n\t}"
        :: "r"(bar), "r"(parity) : "memory");
}

__device__ __forceinline__ float silu_f(float v) { return v / (1.f + expf(-v)); }
__device__ __forceinline__ float softplus_f(float v) {
    return (v > 20.f) ? v : log1pf(expf(v));
}
__device__ __forceinline__ float conv_silu(
    int c, const float* __restrict__ cs, const float* __restrict__ cw)
{
    float v = cs[c * 3 + 0] * cw[c * 4 + 0]
            + cs[c * 3 + 1] * cw[c * 4 + 1]
            + cs[c * 3 + 2] * cw[c * 4 + 2]
            + g_mixed[c]    * cw[c * 4 + 3];
    return silu_f(v);
}
__device__ __forceinline__ float blockSum512(float v, float* red) {
    #pragma unroll
    for (int o = 16; o; o >>= 1) v += __shfl_down_sync(0xffffffffu, v, o);
    int w = threadIdx.x >> 5;
    if ((threadIdx.x & 31) == 0) red[w] = v;
    __syncthreads();
    float r = 0.f;
    #pragma unroll
    for (int i = 0; i < 16; i++) r += red[i];
    __syncthreads();
    return r;
}

// ---------------- K1: ring-2 TMA GEMV (12352 rows x 2048) — R5 proven ------
__global__ __launch_bounds__(256) void k_gemv_in(
    const float* __restrict__ x,
    const float* __restrict__ W_qkv,
    const float* __restrict__ W_z,
    const float* __restrict__ W_b,
    const float* __restrict__ W_a,
    const float* __restrict__ conv_state,
    float* __restrict__ out)
{
    __shared__ __align__(16)  float sx[2048];
    __shared__ __align__(128) float sw[2][4096];
    __shared__ float sred[2][8][2];
    __shared__ __align__(8) unsigned long long mbar[2];

    int tid  = threadIdx.x;
    int warp = tid >> 5;
    int lane = tid & 31;

    #pragma unroll
    for (int i = 0; i < 2; i++)
        ((float4*)sx)[tid + i * 256] = ((const float4*)x)[tid + i * 256];

    uint32_t mb = smem_u32(&mbar[0]);
    if (tid == 0) { mbar_init(mb, 1); mbar_init(mb + 8, 1); }
    __syncthreads();

    int row0 = blockIdx.x * 16;
    const float* wbase;
    if (row0 < 8192)       wbase = W_qkv + (size_t)row0 * 2048;
    else if (row0 < 12288) wbase = W_z   + (size_t)(row0 - 8192) * 2048;
    else if (row0 < 12320) wbase = W_b   + (size_t)(row0 - 12288) * 2048;
    else                   wbase = W_a   + (size_t)(row0 - 12320) * 2048;

    uint32_t sw0 = smem_u32(&sw[0][0]);
    uint32_t sw1 = smem_u32(&sw[1][0]);

    if (tid == 0) {
        mbar_expect_tx(mb, 16384);
        bulk_g2s(sw0, wbase, 16384, mb);
        mbar_expect_tx(mb + 8, 16384);
        bulk_g2s(sw1, wbase + 4096, 16384, mb + 8);
    }

    const float4* x4 = (const float4*)sx;
    float4 xv0 = x4[tid * 2];
    float4 xv1 = x4[tid * 2 + 1];

    #pragma unroll
    for (int i = 0; i < 8; i++) {
        int p = i & 1;
        mbar_wait(mb + p * 8, (i >> 1) & 1);

        const float4* r0 = (const float4*)&sw[p][0];
        const float4* r1 = (const float4*)&sw[p][2048];
        float4 a0 = r0[tid * 2], a1 = r0[tid * 2 + 1];
        float4 b0 = r1[tid * 2], b1 = r1[tid * 2 + 1];
        float pa = a0.x * xv0.x + a0.y * xv0.y + a0.z * xv0.z + a0.w * xv0.w
                 + a1.x * xv1.x + a1.y * xv1.y + a1.z * xv1.z + a1.w * xv1.w;
        float pb = b0.x * xv0.x + b0.y * xv0.y + b0.z * xv0.z + b0.w * xv0.w
                 + b1.x * xv1.x + b1.y * xv1.y + b1.z * xv1.z + b1.w * xv1.w;
        #pragma unroll
        for (int o = 16; o; o >>= 1) {
            pa += __shfl_down_sync(0xffffffffu, pa, o);
            pb += __shfl_down_sync(0xffffffffu, pb, o);
        }
        if (lane == 0) { sred[p][warp][0] = pa; sred[p][warp][1] = pb; }
        __syncthreads();

        if (tid == 0 && i + 2 < 8) {
            mbar_expect_tx(mb + p * 8, 16384);
            bulk_g2s(p ? sw1 : sw0, wbase + (size_t)(i + 2) * 4096, 16384,
                     mb + p * 8);
        }
        if (tid < 2) {
            float acc = 0.f;
            #pragma unroll
            for (int w = 0; w < 8; w++) acc += sred[p][w][tid];
            int r = row0 + i * 2 + tid;
            if (r < 8192) {
                g_mixed[r] = acc;
                float* nc = out + OFF_CONV + (size_t)r * 3;
                __stcs(&nc[0], conv_state[r * 3 + 1]);
                __stcs(&nc[1], conv_state[r * 3 + 2]);
                __stcs(&nc[2], acc);
            } else if (r < 12288) {
                g_z[r - 8192] = acc;
            } else if (r < 12320) {
                g_beta[r - 12288] = acc;
            } else {
                g_a[r - 12320] = acc;
            }
        }
    }
}

// ---------------- K2: per-head delta rule (32 blocks x 512) — R5 proven ----
__global__ __launch_bounds__(512) void k_head(
    const float* __restrict__ state,
    const float* __restrict__ conv_state,
    const float* __restrict__ conv_w,
    const float* __restrict__ A_log,
    const float* __restrict__ dt_bias,
    const float* __restrict__ norm_w,
    float* __restrict__ out)
{
    int h   = blockIdx.x;
    int tid = threadIdx.x;
    int cg  = tid & 31;
    int sl  = tid >> 5;

    __shared__ float sq[128], sk[128], sv[128], sdelta[128];
    __shared__ float red[16];
    __shared__ float skv[16][128], ssqv[16][128];

    if (tid < 128) {
        int grp = h >> 1;
        sq[tid] = conv_silu(grp * 128 + tid,        conv_state, conv_w);
        sk[tid] = conv_silu(2048 + grp * 128 + tid, conv_state, conv_w);
        sv[tid] = conv_silu(4096 + h * 128 + tid,   conv_state, conv_w);
    }
    __syncthreads();

    float q2 = blockSum512(tid < 128 ? sq[tid] * sq[tid] : 0.f, red);
    float k2 = blockSum512(tid < 128 ? sk[tid] * sk[tid] : 0.f, red);
    const float inv_sqrt128 = 0.08838834764831845f;
    if (tid < 128) {
        sq[tid] = sq[tid] * rsqrtf(q2 + 1e-6f) * inv_sqrt128;
        sk[tid] = sk[tid] * rsqrtf(k2 + 1e-6f);
    }
    __syncthreads();
    float qk = blockSum512(tid < 128 ? sq[tid] * sk[tid] : 0.f, red);

    float g    = expf(-expf(A_log[h]) * softplus_f(g_a[h] + dt_bias[h]));
    float beta = 1.f / (1.f + expf(-g_beta[h]));

    const float4* S4 = (const float4*)(state + (size_t)h * 16384);
    float4 sg4[8];
    float4 kv  = make_float4(0.f, 0.f, 0.f, 0.f);
    float4 sqv = make_float4(0.f, 0.f, 0.f, 0.f);
    #pragma unroll
    for (int r = 0; r < 8; r++) {
        int kk = sl * 8 + r;
        float4 s = __ldcs(&S4[kk * 32 + cg]);
        s.x *= g; s.y *= g; s.z *= g; s.w *= g;
        sg4[r] = s;
        float kkv = sk[kk], qqv = sq[kk];
        kv.x  += s.x * kkv; kv.y  += s.y * kkv; kv.z  += s.z * kkv; kv.w  += s.w * kkv;
        sqv.x += s.x * qqv; sqv.y += s.y * qqv; sqv.z += s.z * qqv; sqv.w += s.w * qqv;
    }
    ((float4*)&skv[sl][0])[cg]  = kv;
    ((float4*)&ssqv[sl][0])[cg] = sqv;
    __syncthreads();

    float gated = 0.f;
    if (tid < 128) {
        float kvt = 0.f, sqvt = 0.f;
        #pragma unroll
        for (int s = 0; s < 16; s++) { kvt += skv[s][tid]; sqvt += ssqv[s][tid]; }
        float delta = (sv[tid] - kvt) * beta;
        sdelta[tid] = delta;
        float o = sqvt + delta * qk;
        gated = o * silu_f(g_z[h * 128 + tid]);
    }
    __syncthreads();

    float4 d4 = ((float4*)sdelta)[cg];
    float4* NS4 = (float4*)(out + OFF_STATE + (size_t)h * 16384);
    #pragma unroll
    for (int r = 0; r < 8; r++) {
        int kk = sl * 8 + r;
        float kkv = sk[kk];
        float4 w;
        w.x = sg4[r].x + kkv * d4.x;
        w.y = sg4[r].y + kkv * d4.y;
        w.z = sg4[r].z + kkv * d4.z;
        w.w = sg4[r].w + kkv * d4.w;
        __stcs(&NS4[kk * 32 + cg], w);
    }

    float m = blockSum512(tid < 128 ? gated * gated : 0.f, red) * (1.f / 128.f);
    if (tid < 128)
        g_outflat[h * 128 + tid] = gated * rsqrtf(m + 1e-6f) * norm_w[tid];
}

// ---------------- K3: output GEMV (2048 rows x 4096), MLP-8 + smem x -------
// grid = 1024; block = 2 rows; 4 warps/row, each warp covers 1024 cols
// (8 float4/lane, batched 8-deep). x staged once in smem.
__global__ __launch_bounds__(256, 5) void k_gemv_out(
    const float* __restrict__ W_out, float* __restrict__ out)
{
    __shared__ float so[4096];
    __shared__ float sred[8];
    int tid  = threadIdx.x;
    int warp = tid >> 5;
    int lane = tid & 31;

    #pragma unroll
    for (int i = 0; i < 4; i++)
        ((float4*)so)[tid + i * 256] = ((const float4*)g_outflat)[tid + i * 256];
    __syncthreads();

    int rloc = warp >> 2;               // 0/1 row within block
    int quar = warp & 3;                // quarter of the row (1024 cols)
    int row  = blockIdx.x * 2 + rloc;   // 1024*2 = 2048 rows

    const float4* w4 = (const float4*)(W_out + (size_t)row * 4096) + quar * 256;
    const float4* x4 = (const float4*)so + quar * 256;

    float4 a[8];
    #pragma unroll
    for (int t = 0; t < 8; t++)
        a[t] = __ldcs(&w4[t * 32 + lane]);

    float acc0 = 0.f, acc1 = 0.f;
    #pragma unroll
    for (int t = 0; t < 8; t++) {
        float4 v = x4[t * 32 + lane];
        acc0 += a[t].x * v.x + a[t].y * v.y;
        acc1 += a[t].z * v.z + a[t].w * v.w;
    }
    float acc = acc0 + acc1;
    #pragma unroll
    for (int o = 16; o; o >>= 1) acc += __shfl_down_sync(0xffffffffu, acc, o);
    if (lane == 0) sred[warp] = acc;
    __syncthreads();
    if (tid < 2)
        out[blockIdx.x * 2 + tid] = sred[tid * 4] + sred[tid * 4 + 1]
                                  + sred[tid * 4 + 2] + sred[tid * 4 + 3];
}

// ---------------- launcher --------------------------------------------------
extern "C" void kernel_launch(void* const* d_in, const int* in_sizes, int n_in,
                              void* d_out, int out_size)
{
    const float* x          = (const float*)d_in[0];
    const float* state      = (const float*)d_in[1];
    const float* conv_state = (const float*)d_in[2];
    const float* W_qkv      = (const float*)d_in[3];
    const float* W_z        = (const float*)d_in[4];
    const float* W_b        = (const float*)d_in[5];
    const float* W_a        = (const float*)d_in[6];
    const float* conv_w     = (const float*)d_in[7];
    const float* A_log      = (const float*)d_in[8];
    const float* dt_bias    = (const float*)d_in[9];
    const float* norm_w     = (const float*)d_in[10];
    const float* W_out      = (const float*)d_in[11];
    float* out = (float*)d_out;

    k_gemv_in<<<772, 256>>>(x, W_qkv, W_z, W_b, W_a, conv_state, out);
    k_head<<<32, 512>>>(state, conv_state, conv_w, A_log, dt_bias, norm_w, out);
    k_gemv_out<<<1024, 256>>>(W_out, out);
}